// round 10
// baseline (speedup 1.0000x reference)
#include <cuda_runtime.h>

#define D 8
#define H 256
#define MAXN 100352
#define MASKW (H/32)
#define NPT 4   // nodes per thread in MLP kernels

// ---------------- scratch (device globals; zero-initialized at module load).
// Invariant: accumulator arrays are zero on entry to kernel_launch and are
// re-zeroed by the kernel that consumes them (graph-replay safe).
__device__ float d_mdiag[MAXN*D];
__device__ float d_qs[MAXN*D];     // q * norm_src
__device__ float d_nsrc[MAXN];
__device__ float d_ndst[MAXN];
__device__ int   d_degout[MAXN];   // accumulator (zeroed by k_prep)
__device__ int   d_degin[MAXN];    // accumulator (zeroed by k_prep)
__device__ float d_agg1[MAXN*D];   // accumulator (zeroed by k_mlp_fwd)
__device__ float d_ts[MAXN*D];
__device__ float d_agg2[MAXN*D];   // accumulator (zeroed by k_h)
__device__ float d_h[MAXN*D];
__device__ float d_gH[MAXN*D];     // accumulator (zeroed by k_final)
__device__ float d_gz1d[MAXN*D];
__device__ float d_tmp1[MAXN*D];   // accumulator (zeroed by k_mlp_bwd)
__device__ float d_tmp2[MAXN*D];   // accumulator (zeroed by k_final)
__device__ unsigned d_mask[MAXN*MASKW];

// ---------------- helpers ---------------------------------------------------
__device__ __forceinline__ void red_add_v4(float* p, float4 v) {
    asm volatile("red.global.add.v4.f32 [%0], {%1,%2,%3,%4};"
                 :: "l"(p), "f"(v.x), "f"(v.y), "f"(v.z), "f"(v.w) : "memory");
}

// ---------------- kernels ---------------------------------------------------
__global__ void k_deg(const int* __restrict__ src, const int* __restrict__ dst, int e) {
    int i = blockIdx.x * blockDim.x + threadIdx.x;
    if (i >= e) return;
    atomicAdd(&d_degout[src[i]], 1);
    atomicAdd(&d_degin[dst[i]], 1);
}

// norms, mass diag extraction, qs pre-scale, dHdP output; zero deg counters
__global__ void k_prep(const float* __restrict__ q, const float* __restrict__ p,
                       const float* __restrict__ M, float* __restrict__ out, int n) {
    int i = blockIdx.x * blockDim.x + threadIdx.x;
    if (i >= n) return;
    int dout = d_degout[i], din = d_degin[i];
    d_degout[i] = 0; d_degin[i] = 0;                      // restore invariant
    float ns = (dout > 0) ? rsqrtf((float)dout) : 1.0f;
    float nd = (din  > 0) ? rsqrtf((float)din)  : 1.0f;
    d_nsrc[i] = ns; d_ndst[i] = nd;
#pragma unroll
    for (int d0 = 0; d0 < D; d0++) {
        float m = M[(size_t)i * (D*D) + d0 * (D+1)];   // diagonal entry
        d_mdiag[i*D + d0] = m;
        float qv = q[i*D + d0];
        d_qs[i*D + d0] = qv * ns;
        out[(size_t)i*16 + 8 + d0] = p[i*D + d0] / m;  // dHdP = M^{-1} p
    }
}

// generic 8-float edge gather/scatter (red.v4 atomics), 1 edge/thread
__device__ __forceinline__ void edge_agg(const int* __restrict__ gi, const int* __restrict__ si,
                                         const float* __restrict__ xin, float* xout, int e) {
    int i = blockIdx.x * blockDim.x + threadIdx.x;
    if (i >= e) return;
    int g = gi[i], s = si[i];
    const float4* ps = (const float4*)(xin + (size_t)g * D);
    float4 a = __ldg(ps), b = __ldg(ps + 1);
    float* po = xout + (size_t)s * D;
    red_add_v4(po, a);
    red_add_v4(po + 4, b);
}

__global__ void k_agg1(const int* __restrict__ src, const int* __restrict__ dst, int e)
{ edge_agg(src, dst, d_qs,  d_agg1, e); }
__global__ void k_agg2(const int* __restrict__ src, const int* __restrict__ dst, int e)
{ edge_agg(src, dst, d_ts,  d_agg2, e); }
__global__ void k_aggr2(const int* __restrict__ src, const int* __restrict__ dst, int e)
{ edge_agg(dst, src, d_gz1d, d_tmp2, e); }

// aggr1 folds the ndst scale into the gather: tmp1[src] += gH[dst] * ndst[dst]
__global__ void k_aggr1(const int* __restrict__ src, const int* __restrict__ dst, int e) {
    int i = blockIdx.x * blockDim.x + threadIdx.x;
    if (i >= e) return;
    int g = dst[i], s = src[i];
    float s0 = __ldg(&d_ndst[g]);
    const float4* ps = (const float4*)(d_gH + (size_t)g * D);
    float4 a = __ldg(ps), b = __ldg(ps + 1);
    a.x *= s0; a.y *= s0; a.z *= s0; a.w *= s0;
    b.x *= s0; b.y *= s0; b.z *= s0; b.w *= s0;
    float* po = d_tmp1 + (size_t)s * D;
    red_add_v4(po, a); red_add_v4(po + 4, b);
}

// ---------------- MLP forward, NPT nodes/thread ------------------------------
// z1 = agg1*nd; y1 = z1 W1 + b1; mask; t = relu(y1) W2; ts = t*ns; zero agg1.
// All loop-body stores hit scratch arrays sized MAXN, so no per-node guards.
__global__ __launch_bounds__(256) void k_mlp_fwd(const float* __restrict__ W1,
                                                 const float* __restrict__ b1,
                                                 const float* __restrict__ W2, int n) {
    __shared__ float4 sW1[H][2];   // W1 transposed: sW1[j] = W1[:, j]
    __shared__ float4 sW2[H][2];   // W2[j, :]
    __shared__ float  sb1[H];
    int tid = threadIdx.x;
    {
        int j = tid;
        float4 wa, wb;
        wa.x = W1[0*H + j]; wa.y = W1[1*H + j]; wa.z = W1[2*H + j]; wa.w = W1[3*H + j];
        wb.x = W1[4*H + j]; wb.y = W1[5*H + j]; wb.z = W1[6*H + j]; wb.w = W1[7*H + j];
        sW1[j][0] = wa; sW1[j][1] = wb;
        sW2[j][0] = ((const float4*)W2)[j*2];
        sW2[j][1] = ((const float4*)W2)[j*2 + 1];
        sb1[j] = b1[j];
    }
    __syncthreads();
    int i0 = (blockIdx.x * blockDim.x + tid) * NPT;
    if (i0 >= n) return;
    float z[NPT][D], t[NPT][D];
#pragma unroll
    for (int k = 0; k < NPT; k++) {
        int i = i0 + k;
        float nd = d_ndst[i];
        float4* pz = (float4*)(d_agg1 + (size_t)i * D);
        float4 z0 = pz[0], z1 = pz[1];
        pz[0] = make_float4(0.f,0.f,0.f,0.f);           // restore invariant
        pz[1] = make_float4(0.f,0.f,0.f,0.f);
        z[k][0] = z0.x*nd; z[k][1] = z0.y*nd; z[k][2] = z0.z*nd; z[k][3] = z0.w*nd;
        z[k][4] = z1.x*nd; z[k][5] = z1.y*nd; z[k][6] = z1.z*nd; z[k][7] = z1.w*nd;
#pragma unroll
        for (int d0 = 0; d0 < D; d0++) t[k][d0] = 0.f;
    }
    unsigned mw[NPT] = {0, 0, 0, 0};
#pragma unroll 4
    for (int j = 0; j < H; j++) {
        float4 wa = sW1[j][0], wb = sW1[j][1];
        float  bb = sb1[j];
        float4 va = sW2[j][0], vb = sW2[j][1];
#pragma unroll
        for (int k = 0; k < NPT; k++) {
            float y = bb;
            y += z[k][0]*wa.x + z[k][1]*wa.y + z[k][2]*wa.z + z[k][3]*wa.w;
            y += z[k][4]*wb.x + z[k][5]*wb.y + z[k][6]*wb.z + z[k][7]*wb.w;
            unsigned on = (y > 0.f) ? 1u : 0u;
            mw[k] |= on << (j & 31);
            float r = on ? y : 0.f;
            t[k][0] += r*va.x; t[k][1] += r*va.y; t[k][2] += r*va.z; t[k][3] += r*va.w;
            t[k][4] += r*vb.x; t[k][5] += r*vb.y; t[k][6] += r*vb.z; t[k][7] += r*vb.w;
        }
        if ((j & 31) == 31) {
#pragma unroll
            for (int k = 0; k < NPT; k++) {
                d_mask[(size_t)(i0 + k)*MASKW + (j >> 5)] = mw[k];
                mw[k] = 0;
            }
        }
    }
#pragma unroll
    for (int k = 0; k < NPT; k++) {
        int i = i0 + k;
        float ns = d_nsrc[i];
        float4* po = (float4*)(d_ts + (size_t)i * D);
        po[0] = make_float4(t[k][0]*ns, t[k][1]*ns, t[k][2]*ns, t[k][3]*ns);
        po[1] = make_float4(t[k][4]*ns, t[k][5]*ns, t[k][6]*ns, t[k][7]*ns);
    }
}

// h = agg2*nd + b2 + q; zero agg2
__global__ void k_h(const float* __restrict__ q, const float* __restrict__ b2, int n) {
    int i = blockIdx.x * blockDim.x + threadIdx.x;
    if (i >= n) return;
    float nd = d_ndst[i];
#pragma unroll
    for (int d0 = 0; d0 < D; d0++) {
        d_h[i*D + d0] = d_agg2[i*D + d0] * nd + __ldg(&b2[d0]) + q[i*D + d0];
        d_agg2[i*D + d0] = 0.f;                           // restore invariant
    }
}

// pairwise force: gH[src] += a, gH[dst] -= a ; a = -0.5*g*c*(hs-hd)/r^3
__global__ void k_force(const int* __restrict__ src, const int* __restrict__ dst,
                        const float* __restrict__ grav, int e) {
    int i = blockIdx.x * blockDim.x + threadIdx.x;
    if (i >= e) return;
    int s = src[i], t = dst[i];
    const float4* phs = (const float4*)(d_h + (size_t)s * D);
    const float4* phd = (const float4*)(d_h + (size_t)t * D);
    const float4* pms = (const float4*)(d_mdiag + (size_t)s * D);
    const float4* pmd = (const float4*)(d_mdiag + (size_t)t * D);
    float4 hs0 = __ldg(phs), hs1 = __ldg(phs+1);
    float4 hd0 = __ldg(phd), hd1 = __ldg(phd+1);
    float4 ms0 = __ldg(pms), ms1 = __ldg(pms+1);
    float4 md0 = __ldg(pmd), md1 = __ldg(pmd+1);
    float c = ms0.x*md0.x + ms0.y*md0.y + ms0.z*md0.z + ms0.w*md0.w
            + ms1.x*md1.x + ms1.y*md1.y + ms1.z*md1.z + ms1.w*md1.w;
    float4 f0, f1;
    f0.x = hs0.x - hd0.x; f0.y = hs0.y - hd0.y; f0.z = hs0.z - hd0.z; f0.w = hs0.w - hd0.w;
    f1.x = hs1.x - hd1.x; f1.y = hs1.y - hd1.y; f1.z = hs1.z - hd1.z; f1.w = hs1.w - hd1.w;
    float r2 = f0.x*f0.x + f0.y*f0.y + f0.z*f0.z + f0.w*f0.w
             + f1.x*f1.x + f1.y*f1.y + f1.z*f1.z + f1.w*f1.w;
    float inv = rsqrtf(r2);
    float coef = -0.5f * __ldg(grav) * c * inv * inv * inv;
    float4 a0, a1, n0, n1;
    a0.x = coef*f0.x; a0.y = coef*f0.y; a0.z = coef*f0.z; a0.w = coef*f0.w;
    a1.x = coef*f1.x; a1.y = coef*f1.y; a1.z = coef*f1.z; a1.w = coef*f1.w;
    n0.x = -a0.x; n0.y = -a0.y; n0.z = -a0.z; n0.w = -a0.w;
    n1.x = -a1.x; n1.y = -a1.y; n1.z = -a1.z; n1.w = -a1.w;
    float* ps = d_gH + (size_t)s * D;
    float* pt = d_gH + (size_t)t * D;
    red_add_v4(ps, a0); red_add_v4(ps + 4, a1);
    red_add_v4(pt, n0); red_add_v4(pt + 4, n1);
}

// ---------------- MLP backward, NPT nodes/thread -----------------------------
// gt = tmp1*ns; gh1 = gt W2^T; *mask; gz1 = gh1 W1^T; gz1d = gz1*nd; zero tmp1.
__global__ __launch_bounds__(256) void k_mlp_bwd(const float* __restrict__ W1,
                                                 const float* __restrict__ W2, int n) {
    __shared__ float4 sW1[H][2];
    __shared__ float4 sW2[H][2];
    int tid = threadIdx.x;
    {
        int j = tid;
        float4 wa, wb;
        wa.x = W1[0*H + j]; wa.y = W1[1*H + j]; wa.z = W1[2*H + j]; wa.w = W1[3*H + j];
        wb.x = W1[4*H + j]; wb.y = W1[5*H + j]; wb.z = W1[6*H + j]; wb.w = W1[7*H + j];
        sW1[j][0] = wa; sW1[j][1] = wb;
        sW2[j][0] = ((const float4*)W2)[j*2];
        sW2[j][1] = ((const float4*)W2)[j*2 + 1];
    }
    __syncthreads();
    int i0 = (blockIdx.x * blockDim.x + tid) * NPT;
    if (i0 >= n) return;
    float g[NPT][D], zc[NPT][D];
#pragma unroll
    for (int k = 0; k < NPT; k++) {
        int i = i0 + k;
        float ns = d_nsrc[i];
        float4* pg = (float4*)(d_tmp1 + (size_t)i * D);
        float4 g0 = pg[0], g1 = pg[1];
        pg[0] = make_float4(0.f,0.f,0.f,0.f);           // restore invariant
        pg[1] = make_float4(0.f,0.f,0.f,0.f);
        g[k][0] = g0.x*ns; g[k][1] = g0.y*ns; g[k][2] = g0.z*ns; g[k][3] = g0.w*ns;
        g[k][4] = g1.x*ns; g[k][5] = g1.y*ns; g[k][6] = g1.z*ns; g[k][7] = g1.w*ns;
#pragma unroll
        for (int d0 = 0; d0 < D; d0++) zc[k][d0] = 0.f;
    }
    unsigned mw[NPT];
#pragma unroll 4
    for (int j = 0; j < H; j++) {
        if ((j & 31) == 0) {
#pragma unroll
            for (int k = 0; k < NPT; k++)
                mw[k] = d_mask[(size_t)(i0 + k)*MASKW + (j >> 5)];
        }
        float4 va = sW2[j][0], vb = sW2[j][1];
        float4 wa = sW1[j][0], wb = sW1[j][1];
#pragma unroll
        for (int k = 0; k < NPT; k++) {
            float gh = g[k][0]*va.x + g[k][1]*va.y + g[k][2]*va.z + g[k][3]*va.w
                     + g[k][4]*vb.x + g[k][5]*vb.y + g[k][6]*vb.z + g[k][7]*vb.w;
            gh *= (float)((mw[k] >> (j & 31)) & 1u);     // relu'(y1)
            zc[k][0] += gh*wa.x; zc[k][1] += gh*wa.y; zc[k][2] += gh*wa.z; zc[k][3] += gh*wa.w;
            zc[k][4] += gh*wb.x; zc[k][5] += gh*wb.y; zc[k][6] += gh*wb.z; zc[k][7] += gh*wb.w;
        }
    }
#pragma unroll
    for (int k = 0; k < NPT; k++) {
        int i = i0 + k;
        float nd = d_ndst[i];
        float4* po = (float4*)(d_gz1d + (size_t)i * D);
        po[0] = make_float4(zc[k][0]*nd, zc[k][1]*nd, zc[k][2]*nd, zc[k][3]*nd);
        po[1] = make_float4(zc[k][4]*nd, zc[k][5]*nd, zc[k][6]*nd, zc[k][7]*nd);
    }
}

// out[:, 0:8] = gH + nsrc * tmp2; zero gH, tmp2
__global__ void k_final(float* __restrict__ out, int n) {
    int i = blockIdx.x * blockDim.x + threadIdx.x;
    if (i >= n) return;
    float ns = d_nsrc[i];
#pragma unroll
    for (int d0 = 0; d0 < D; d0++) {
        out[(size_t)i*16 + d0] = d_gH[i*D + d0] + ns * d_tmp2[i*D + d0];
        d_gH[i*D + d0] = 0.f;                             // restore invariant
        d_tmp2[i*D + d0] = 0.f;
    }
}

// ---------------- launch ----------------------------------------------------
extern "C" void kernel_launch(void* const* d_in, const int* in_sizes, int n_in,
                              void* d_out, int out_size) {
    const float* q    = (const float*)d_in[0];
    const float* p    = (const float*)d_in[1];
    const float* M    = (const float*)d_in[2];
    const int*   src  = (const int*)  d_in[3];
    const int*   dst  = (const int*)  d_in[4];
    const float* W1   = (const float*)d_in[5];
    const float* b1   = (const float*)d_in[6];
    const float* W2   = (const float*)d_in[7];
    const float* b2   = (const float*)d_in[8];
    const float* grav = (const float*)d_in[9];
    float* out = (float*)d_out;

    int n = in_sizes[0] / D;
    int e = in_sizes[3];
    int nb_n   = (n + 255) / 256;
    int nb_n4  = ((n + NPT - 1) / NPT + 255) / 256;
    int nb_e   = (e + 255) / 256;

    k_deg    <<<nb_e,  256>>>(src, dst, e);
    k_prep   <<<nb_n,  256>>>(q, p, M, out, n);
    k_agg1   <<<nb_e,  256>>>(src, dst, e);
    k_mlp_fwd<<<nb_n4, 256>>>(W1, b1, W2, n);
    k_agg2   <<<nb_e,  256>>>(src, dst, e);
    k_h      <<<nb_n,  256>>>(q, b2, n);
    k_force  <<<nb_e,  256>>>(src, dst, grav, e);
    k_aggr1  <<<nb_e,  256>>>(src, dst, e);
    k_mlp_bwd<<<nb_n4, 256>>>(W1, W2, n);
    k_aggr2  <<<nb_e,  256>>>(src, dst, e);
    k_final  <<<nb_n,  256>>>(out, n);
}

// round 11
// speedup vs baseline: 1.0393x; 1.0393x over previous
#include <cuda_runtime.h>

#define D 8
#define H 256
#define MAXN 100352
#define MASKW (H/32)
typedef unsigned long long u64;

// ---------------- scratch (device globals; zero-initialized at module load).
// Invariant: accumulator arrays are zero on entry to kernel_launch and are
// re-zeroed by the kernel that consumes them (graph-replay safe).
__device__ float d_mdiag[MAXN*D];
__device__ float d_qs[MAXN*D];     // q * norm_src
__device__ float d_nsrc[MAXN];
__device__ float d_ndst[MAXN];
__device__ int   d_degout[MAXN];   // accumulator (zeroed by k_prep)
__device__ int   d_degin[MAXN];    // accumulator (zeroed by k_prep)
__device__ float d_agg1[MAXN*D];   // accumulator (zeroed by k_mlp_fwd)
__device__ float d_ts[MAXN*D];
__device__ float d_agg2[MAXN*D];   // accumulator (zeroed by k_h)
__device__ float d_h[MAXN*D];
__device__ float d_gH[MAXN*D];     // accumulator (zeroed by k_final)
__device__ float d_gz1d[MAXN*D];
__device__ float d_tmp1[MAXN*D];   // accumulator (zeroed by k_mlp_bwd)
__device__ float d_tmp2[MAXN*D];   // accumulator (zeroed by k_final)
__device__ unsigned d_mask[MAXN*MASKW];

// ---------------- helpers ---------------------------------------------------
__device__ __forceinline__ void red_add_v4(float* p, float4 v) {
    asm volatile("red.global.add.v4.f32 [%0], {%1,%2,%3,%4};"
                 :: "l"(p), "f"(v.x), "f"(v.y), "f"(v.z), "f"(v.w) : "memory");
}
__device__ __forceinline__ u64 pk(float a, float b) {
    u64 r; asm("mov.b64 %0, {%1,%2};" : "=l"(r) : "f"(a), "f"(b)); return r;
}
__device__ __forceinline__ void upk(u64 v, float& a, float& b) {
    asm("mov.b64 {%0,%1}, %2;" : "=f"(a), "=f"(b) : "l"(v));
}
__device__ __forceinline__ u64 fma2(u64 a, u64 b, u64 c) {
    u64 r; asm("fma.rn.f32x2 %0, %1, %2, %3;" : "=l"(r) : "l"(a), "l"(b), "l"(c)); return r;
}

// ---------------- kernels ---------------------------------------------------
__global__ void k_deg(const int* __restrict__ src, const int* __restrict__ dst, int e) {
    int i = blockIdx.x * blockDim.x + threadIdx.x;
    if (i >= e) return;
    atomicAdd(&d_degout[src[i]], 1);
    atomicAdd(&d_degin[dst[i]], 1);
}

// norms, mass diag extraction, qs pre-scale, dHdP output; zero deg counters
__global__ void k_prep(const float* __restrict__ q, const float* __restrict__ p,
                       const float* __restrict__ M, float* __restrict__ out, int n) {
    int i = blockIdx.x * blockDim.x + threadIdx.x;
    if (i >= n) return;
    int dout = d_degout[i], din = d_degin[i];
    d_degout[i] = 0; d_degin[i] = 0;                      // restore invariant
    float ns = (dout > 0) ? rsqrtf((float)dout) : 1.0f;
    float nd = (din  > 0) ? rsqrtf((float)din)  : 1.0f;
    d_nsrc[i] = ns; d_ndst[i] = nd;
#pragma unroll
    for (int d0 = 0; d0 < D; d0++) {
        float m = M[(size_t)i * (D*D) + d0 * (D+1)];   // diagonal entry
        d_mdiag[i*D + d0] = m;
        float qv = q[i*D + d0];
        d_qs[i*D + d0] = qv * ns;
        out[(size_t)i*16 + 8 + d0] = p[i*D + d0] / m;  // dHdP = M^{-1} p
    }
}

// generic 8-float edge gather/scatter (red.v4 atomics), 1 edge/thread
__device__ __forceinline__ void edge_agg(const int* __restrict__ gi, const int* __restrict__ si,
                                         const float* __restrict__ xin, float* xout, int e) {
    int i = blockIdx.x * blockDim.x + threadIdx.x;
    if (i >= e) return;
    int g = gi[i], s = si[i];
    const float4* ps = (const float4*)(xin + (size_t)g * D);
    float4 a = __ldg(ps), b = __ldg(ps + 1);
    float* po = xout + (size_t)s * D;
    red_add_v4(po, a);
    red_add_v4(po + 4, b);
}

__global__ void k_agg1(const int* __restrict__ src, const int* __restrict__ dst, int e)
{ edge_agg(src, dst, d_qs,  d_agg1, e); }
__global__ void k_agg2(const int* __restrict__ src, const int* __restrict__ dst, int e)
{ edge_agg(src, dst, d_ts,  d_agg2, e); }
__global__ void k_aggr2(const int* __restrict__ src, const int* __restrict__ dst, int e)
{ edge_agg(dst, src, d_gz1d, d_tmp2, e); }

// aggr1 folds the ndst scale into the gather: tmp1[src] += gH[dst] * ndst[dst]
__global__ void k_aggr1(const int* __restrict__ src, const int* __restrict__ dst, int e) {
    int i = blockIdx.x * blockDim.x + threadIdx.x;
    if (i >= e) return;
    int g = dst[i], s = src[i];
    float s0 = __ldg(&d_ndst[g]);
    const float4* ps = (const float4*)(d_gH + (size_t)g * D);
    float4 a = __ldg(ps), b = __ldg(ps + 1);
    a.x *= s0; a.y *= s0; a.z *= s0; a.w *= s0;
    b.x *= s0; b.y *= s0; b.z *= s0; b.w *= s0;
    float* po = d_tmp1 + (size_t)s * D;
    red_add_v4(po, a); red_add_v4(po + 4, b);
}

// ---------------- MLP forward: 2 nodes/thread packed in f32x2 ----------------
// Weights staged in shared PRE-DUPLICATED: one u64 = (w, w) per scalar weight,
// so the inner loop has zero pack movs for weights. Accumulators pack the two
// nodes: acc = (y_n0, y_n1), t[d] = (t_n0[d], t_n1[d]).
__global__ __launch_bounds__(128) void k_mlp_fwd(const float* __restrict__ W1,
                                                 const float* __restrict__ b1,
                                                 const float* __restrict__ W2, int n) {
    __shared__ ulonglong2 sW1d[H][4];  // [j][dd]: (dup(W1[2dd][j]), dup(W1[2dd+1][j]))
    __shared__ ulonglong2 sW2d[H][4];  // [j][dd]: (dup(W2[j][2dd]), dup(W2[j][2dd+1]))
    __shared__ u64        sb1d[H];     // dup(b1[j])
    int tid = threadIdx.x;
    for (int j = tid; j < H; j += 128) {
#pragma unroll
        for (int dd = 0; dd < 4; dd++) {
            float wa = W1[(2*dd)*H + j], wb = W1[(2*dd+1)*H + j];
            sW1d[j][dd] = make_ulonglong2(pk(wa, wa), pk(wb, wb));
            float va = W2[j*D + 2*dd], vb = W2[j*D + 2*dd + 1];
            sW2d[j][dd] = make_ulonglong2(pk(va, va), pk(vb, vb));
        }
        float bb = b1[j];
        sb1d[j] = pk(bb, bb);
    }
    __syncthreads();
    int i0 = (blockIdx.x * 128 + tid) * 2;
    if (i0 >= n) return;
    // load + scale + zero the two nodes' aggregates, pack along nodes
    u64 zp[D], tp[D];
    {
        float nd0 = d_ndst[i0], nd1 = d_ndst[i0 + 1];
        float4* pz0 = (float4*)(d_agg1 + (size_t)i0 * D);
        float4 a0 = pz0[0], a1 = pz0[1], b0 = pz0[2], b1v = pz0[3]; // node i0: a0,a1; node i0+1: b0,b1v
        pz0[0] = make_float4(0.f,0.f,0.f,0.f);            // restore invariant
        pz0[1] = make_float4(0.f,0.f,0.f,0.f);
        pz0[2] = make_float4(0.f,0.f,0.f,0.f);
        pz0[3] = make_float4(0.f,0.f,0.f,0.f);
        zp[0] = pk(a0.x*nd0, b0.x*nd1);  zp[1] = pk(a0.y*nd0, b0.y*nd1);
        zp[2] = pk(a0.z*nd0, b0.z*nd1);  zp[3] = pk(a0.w*nd0, b0.w*nd1);
        zp[4] = pk(a1.x*nd0, b1v.x*nd1); zp[5] = pk(a1.y*nd0, b1v.y*nd1);
        zp[6] = pk(a1.z*nd0, b1v.z*nd1); zp[7] = pk(a1.w*nd0, b1v.w*nd1);
        u64 z2 = pk(0.f, 0.f);
#pragma unroll
        for (int d0 = 0; d0 < D; d0++) tp[d0] = z2;
    }
    unsigned mw0 = 0, mw1 = 0;
#pragma unroll 4
    for (int j = 0; j < H; j++) {
        ulonglong2 wA = sW1d[j][0], wB = sW1d[j][1], wC = sW1d[j][2], wD2 = sW1d[j][3];
        u64 acc = sb1d[j];
        acc = fma2(zp[0], wA.x, acc); acc = fma2(zp[1], wA.y, acc);
        acc = fma2(zp[2], wB.x, acc); acc = fma2(zp[3], wB.y, acc);
        acc = fma2(zp[4], wC.x, acc); acc = fma2(zp[5], wC.y, acc);
        acc = fma2(zp[6], wD2.x, acc); acc = fma2(zp[7], wD2.y, acc);
        float y0, y1; upk(acc, y0, y1);
        mw0 |= (y0 > 0.f ? 1u : 0u) << (j & 31);
        mw1 |= (y1 > 0.f ? 1u : 0u) << (j & 31);
        u64 rr = pk(fmaxf(y0, 0.f), fmaxf(y1, 0.f));
        ulonglong2 vA = sW2d[j][0], vB = sW2d[j][1], vC = sW2d[j][2], vD2 = sW2d[j][3];
        tp[0] = fma2(rr, vA.x, tp[0]); tp[1] = fma2(rr, vA.y, tp[1]);
        tp[2] = fma2(rr, vB.x, tp[2]); tp[3] = fma2(rr, vB.y, tp[3]);
        tp[4] = fma2(rr, vC.x, tp[4]); tp[5] = fma2(rr, vC.y, tp[5]);
        tp[6] = fma2(rr, vD2.x, tp[6]); tp[7] = fma2(rr, vD2.y, tp[7]);
        if ((j & 31) == 31) {
            d_mask[(size_t)i0*MASKW + (j >> 5)] = mw0;
            d_mask[(size_t)(i0+1)*MASKW + (j >> 5)] = mw1;
            mw0 = 0; mw1 = 0;
        }
    }
    {
        float ns0 = d_nsrc[i0], ns1 = d_nsrc[i0 + 1];
        float t0[D], t1[D];
#pragma unroll
        for (int d0 = 0; d0 < D; d0++) upk(tp[d0], t0[d0], t1[d0]);
        float4* po = (float4*)(d_ts + (size_t)i0 * D);
        po[0] = make_float4(t0[0]*ns0, t0[1]*ns0, t0[2]*ns0, t0[3]*ns0);
        po[1] = make_float4(t0[4]*ns0, t0[5]*ns0, t0[6]*ns0, t0[7]*ns0);
        po[2] = make_float4(t1[0]*ns1, t1[1]*ns1, t1[2]*ns1, t1[3]*ns1);
        po[3] = make_float4(t1[4]*ns1, t1[5]*ns1, t1[6]*ns1, t1[7]*ns1);
    }
}

// h = agg2*nd + b2 + q; zero agg2
__global__ void k_h(const float* __restrict__ q, const float* __restrict__ b2, int n) {
    int i = blockIdx.x * blockDim.x + threadIdx.x;
    if (i >= n) return;
    float nd = d_ndst[i];
#pragma unroll
    for (int d0 = 0; d0 < D; d0++) {
        d_h[i*D + d0] = d_agg2[i*D + d0] * nd + __ldg(&b2[d0]) + q[i*D + d0];
        d_agg2[i*D + d0] = 0.f;                           // restore invariant
    }
}

// pairwise force: gH[src] += a, gH[dst] -= a ; a = -0.5*g*c*(hs-hd)/r^3
__global__ void k_force(const int* __restrict__ src, const int* __restrict__ dst,
                        const float* __restrict__ grav, int e) {
    int i = blockIdx.x * blockDim.x + threadIdx.x;
    if (i >= e) return;
    int s = src[i], t = dst[i];
    const float4* phs = (const float4*)(d_h + (size_t)s * D);
    const float4* phd = (const float4*)(d_h + (size_t)t * D);
    const float4* pms = (const float4*)(d_mdiag + (size_t)s * D);
    const float4* pmd = (const float4*)(d_mdiag + (size_t)t * D);
    float4 hs0 = __ldg(phs), hs1 = __ldg(phs+1);
    float4 hd0 = __ldg(phd), hd1 = __ldg(phd+1);
    float4 ms0 = __ldg(pms), ms1 = __ldg(pms+1);
    float4 md0 = __ldg(pmd), md1 = __ldg(pmd+1);
    float c = ms0.x*md0.x + ms0.y*md0.y + ms0.z*md0.z + ms0.w*md0.w
            + ms1.x*md1.x + ms1.y*md1.y + ms1.z*md1.z + ms1.w*md1.w;
    float4 f0, f1;
    f0.x = hs0.x - hd0.x; f0.y = hs0.y - hd0.y; f0.z = hs0.z - hd0.z; f0.w = hs0.w - hd0.w;
    f1.x = hs1.x - hd1.x; f1.y = hs1.y - hd1.y; f1.z = hs1.z - hd1.z; f1.w = hs1.w - hd1.w;
    float r2 = f0.x*f0.x + f0.y*f0.y + f0.z*f0.z + f0.w*f0.w
             + f1.x*f1.x + f1.y*f1.y + f1.z*f1.z + f1.w*f1.w;
    float inv = rsqrtf(r2);
    float coef = -0.5f * __ldg(grav) * c * inv * inv * inv;
    float4 a0, a1, n0, n1;
    a0.x = coef*f0.x; a0.y = coef*f0.y; a0.z = coef*f0.z; a0.w = coef*f0.w;
    a1.x = coef*f1.x; a1.y = coef*f1.y; a1.z = coef*f1.z; a1.w = coef*f1.w;
    n0.x = -a0.x; n0.y = -a0.y; n0.z = -a0.z; n0.w = -a0.w;
    n1.x = -a1.x; n1.y = -a1.y; n1.z = -a1.z; n1.w = -a1.w;
    float* ps = d_gH + (size_t)s * D;
    float* pt = d_gH + (size_t)t * D;
    red_add_v4(ps, a0); red_add_v4(ps + 4, a1);
    red_add_v4(pt, n0); red_add_v4(pt + 4, n1);
}

// ---------------- MLP backward: 2 nodes/thread packed in f32x2 ---------------
// gt = tmp1*ns; gh1 = gt W2^T; *mask; gz1 = gh1 W1^T; gz1d = gz1*nd; zero tmp1.
__global__ __launch_bounds__(128) void k_mlp_bwd(const float* __restrict__ W1,
                                                 const float* __restrict__ W2, int n) {
    __shared__ ulonglong2 sW1d[H][4];  // duplicated W1 columns
    __shared__ ulonglong2 sW2d[H][4];  // duplicated W2 rows
    int tid = threadIdx.x;
    for (int j = tid; j < H; j += 128) {
#pragma unroll
        for (int dd = 0; dd < 4; dd++) {
            float wa = W1[(2*dd)*H + j], wb = W1[(2*dd+1)*H + j];
            sW1d[j][dd] = make_ulonglong2(pk(wa, wa), pk(wb, wb));
            float va = W2[j*D + 2*dd], vb = W2[j*D + 2*dd + 1];
            sW2d[j][dd] = make_ulonglong2(pk(va, va), pk(vb, vb));
        }
    }
    __syncthreads();
    int i0 = (blockIdx.x * 128 + tid) * 2;
    if (i0 >= n) return;
    u64 gp[D], zcp[D];
    {
        float ns0 = d_nsrc[i0], ns1 = d_nsrc[i0 + 1];
        float4* pg = (float4*)(d_tmp1 + (size_t)i0 * D);
        float4 a0 = pg[0], a1 = pg[1], b0 = pg[2], b1v = pg[3];
        pg[0] = make_float4(0.f,0.f,0.f,0.f);             // restore invariant
        pg[1] = make_float4(0.f,0.f,0.f,0.f);
        pg[2] = make_float4(0.f,0.f,0.f,0.f);
        pg[3] = make_float4(0.f,0.f,0.f,0.f);
        gp[0] = pk(a0.x*ns0, b0.x*ns1);  gp[1] = pk(a0.y*ns0, b0.y*ns1);
        gp[2] = pk(a0.z*ns0, b0.z*ns1);  gp[3] = pk(a0.w*ns0, b0.w*ns1);
        gp[4] = pk(a1.x*ns0, b1v.x*ns1); gp[5] = pk(a1.y*ns0, b1v.y*ns1);
        gp[6] = pk(a1.z*ns0, b1v.z*ns1); gp[7] = pk(a1.w*ns0, b1v.w*ns1);
        u64 z2 = pk(0.f, 0.f);
#pragma unroll
        for (int d0 = 0; d0 < D; d0++) zcp[d0] = z2;
    }
    unsigned mw0 = 0, mw1 = 0;
#pragma unroll 4
    for (int j = 0; j < H; j++) {
        if ((j & 31) == 0) {
            mw0 = d_mask[(size_t)i0*MASKW + (j >> 5)];
            mw1 = d_mask[(size_t)(i0+1)*MASKW + (j >> 5)];
        }
        ulonglong2 vA = sW2d[j][0], vB = sW2d[j][1], vC = sW2d[j][2], vD2 = sW2d[j][3];
        u64 acc = fma2(gp[0], vA.x, pk(0.f, 0.f));
        acc = fma2(gp[1], vA.y, acc);
        acc = fma2(gp[2], vB.x, acc); acc = fma2(gp[3], vB.y, acc);
        acc = fma2(gp[4], vC.x, acc); acc = fma2(gp[5], vC.y, acc);
        acc = fma2(gp[6], vD2.x, acc); acc = fma2(gp[7], vD2.y, acc);
        float gh0, gh1; upk(acc, gh0, gh1);
        gh0 *= (float)((mw0 >> (j & 31)) & 1u);          // relu'(y1) node 0
        gh1 *= (float)((mw1 >> (j & 31)) & 1u);          // relu'(y1) node 1
        u64 gg = pk(gh0, gh1);
        ulonglong2 wA = sW1d[j][0], wB = sW1d[j][1], wC = sW1d[j][2], wD2 = sW1d[j][3];
        zcp[0] = fma2(gg, wA.x, zcp[0]); zcp[1] = fma2(gg, wA.y, zcp[1]);
        zcp[2] = fma2(gg, wB.x, zcp[2]); zcp[3] = fma2(gg, wB.y, zcp[3]);
        zcp[4] = fma2(gg, wC.x, zcp[4]); zcp[5] = fma2(gg, wC.y, zcp[5]);
        zcp[6] = fma2(gg, wD2.x, zcp[6]); zcp[7] = fma2(gg, wD2.y, zcp[7]);
    }
    {
        float nd0 = d_ndst[i0], nd1 = d_ndst[i0 + 1];
        float z0[D], z1[D];
#pragma unroll
        for (int d0 = 0; d0 < D; d0++) upk(zcp[d0], z0[d0], z1[d0]);
        float4* po = (float4*)(d_gz1d + (size_t)i0 * D);
        po[0] = make_float4(z0[0]*nd0, z0[1]*nd0, z0[2]*nd0, z0[3]*nd0);
        po[1] = make_float4(z0[4]*nd0, z0[5]*nd0, z0[6]*nd0, z0[7]*nd0);
        po[2] = make_float4(z1[0]*nd1, z1[1]*nd1, z1[2]*nd1, z1[3]*nd1);
        po[3] = make_float4(z1[4]*nd1, z1[5]*nd1, z1[6]*nd1, z1[7]*nd1);
    }
}

// out[:, 0:8] = gH + nsrc * tmp2; zero gH, tmp2
__global__ void k_final(float* __restrict__ out, int n) {
    int i = blockIdx.x * blockDim.x + threadIdx.x;
    if (i >= n) return;
    float ns = d_nsrc[i];
#pragma unroll
    for (int d0 = 0; d0 < D; d0++) {
        out[(size_t)i*16 + d0] = d_gH[i*D + d0] + ns * d_tmp2[i*D + d0];
        d_gH[i*D + d0] = 0.f;                             // restore invariant
        d_tmp2[i*D + d0] = 0.f;
    }
}

// ---------------- launch ----------------------------------------------------
extern "C" void kernel_launch(void* const* d_in, const int* in_sizes, int n_in,
                              void* d_out, int out_size) {
    const float* q    = (const float*)d_in[0];
    const float* p    = (const float*)d_in[1];
    const float* M    = (const float*)d_in[2];
    const int*   src  = (const int*)  d_in[3];
    const int*   dst  = (const int*)  d_in[4];
    const float* W1   = (const float*)d_in[5];
    const float* b1   = (const float*)d_in[6];
    const float* W2   = (const float*)d_in[7];
    const float* b2   = (const float*)d_in[8];
    const float* grav = (const float*)d_in[9];
    float* out = (float*)d_out;

    int n = in_sizes[0] / D;
    int e = in_sizes[3];
    int nb_n  = (n + 255) / 256;
    int nb_n2 = ((n + 1) / 2 + 127) / 128;   // MLP: 2 nodes/thread, block=128
    int nb_e  = (e + 255) / 256;

    k_deg    <<<nb_e,  256>>>(src, dst, e);
    k_prep   <<<nb_n,  256>>>(q, p, M, out, n);
    k_agg1   <<<nb_e,  256>>>(src, dst, e);
    k_mlp_fwd<<<nb_n2, 128>>>(W1, b1, W2, n);
    k_agg2   <<<nb_e,  256>>>(src, dst, e);
    k_h      <<<nb_n,  256>>>(q, b2, n);
    k_force  <<<nb_e,  256>>>(src, dst, grav, e);
    k_aggr1  <<<nb_e,  256>>>(src, dst, e);
    k_mlp_bwd<<<nb_n2, 128>>>(W1, W2, n);
    k_aggr2  <<<nb_e,  256>>>(src, dst, e);
    k_final  <<<nb_n,  256>>>(out, n);
}